// round 13
// baseline (speedup 1.0000x reference)
#include <cuda_runtime.h>
#include <cuda_fp16.h>
#include <cstdint>
#include <cstdio>

#define V_N 65536
#define E_N 196608
#define M_SEG 64
#define NN1 128
#define EPS_BN 1e-5f

// ---------------- device scratch (no allocations allowed) ----------------
__device__ float g_y[262144];      // layer-1 gathered feats (V*3)
__device__ __half g_zh[67108864];  // gemm output fp16, up to V*1024
__device__ __half g_xh[33554432];  // activation fp16, V*512 max
__device__ __half g_yh[33554432];  // gathered fp16
__device__ __half g_wt2[262144];   // layer-2 weights [512][512] fp16
__device__ __half g_wt3[1048576];  // layer-3 weights [1024][1024] fp16
__device__ int   g_deg[V_N];
__device__ int   g_off[V_N + 1];
__device__ int   g_pos[V_N];
__device__ int   g_adj[2 * E_N];
__device__ float g_colsum[1792];   // per-layer regions: L1 @0, L2 @256, L3 @768
__device__ float g_colsq[1792];
__device__ float g_pooled[M_SEG * 1024];
__device__ float g_cnt[M_SEG];
__device__ float g_h[M_SEG * NN1];
__device__ unsigned long long g_ts[32];

// ---------------- timing stamps ----------------
__global__ void k_stamp(int i) {
    unsigned long long t;
    asm volatile("mov.u64 %0, %%globaltimer;" : "=l"(t));
    g_ts[i] = t;
}

__global__ void k_report(int n) {
    printf("STAGE_TIMES_US:");
    for (int i = 1; i < n; i++)
        printf(" %d:%.1f", i, (double)(g_ts[i] - g_ts[i - 1]) * 1e-3);
    printf(" total:%.1f\n", (double)(g_ts[n - 1] - g_ts[0]) * 1e-3);
}

// ---------------- PTX helpers ----------------
__device__ __forceinline__ uint32_t smem_u32(const void* p) {
    uint32_t a;
    asm("{ .reg .u64 t; cvta.to.shared.u64 t, %1; cvt.u32.u64 %0, t; }"
        : "=r"(a) : "l"(p));
    return a;
}

#define LDSM_X4(r, addr) \
    asm volatile("ldmatrix.sync.aligned.m8n8.x4.shared.b16 {%0,%1,%2,%3}, [%4];" \
                 : "=r"((r)[0]), "=r"((r)[1]), "=r"((r)[2]), "=r"((r)[3]) : "r"(addr))

#define MMA16816H(d, a, b) \
    asm volatile("mma.sync.aligned.m16n8k16.row.col.f32.f16.f16.f32 " \
                 "{%0,%1,%2,%3}, {%4,%5,%6,%7}, {%8,%9}, {%0,%1,%2,%3};" \
                 : "+f"((d)[0]), "+f"((d)[1]), "+f"((d)[2]), "+f"((d)[3]) \
                 : "r"((a)[0]), "r"((a)[1]), "r"((a)[2]), "r"((a)[3]), \
                   "r"((b)[0]), "r"((b)[1]))

#define CP16(saddr, gptr) \
    asm volatile("cp.async.cg.shared.global [%0], [%1], 16;" \
                 :: "r"(saddr), "l"(gptr) : "memory")
#define CP_COMMIT() asm volatile("cp.async.commit_group;" ::: "memory")
#define CP_WAIT1()  asm volatile("cp.async.wait_group 1;" ::: "memory")
#define CP_WAIT0()  asm volatile("cp.async.wait_group 0;" ::: "memory")

// ---------------- fused init ----------------
__global__ void k_init(const int* __restrict__ vidx) {
    if (blockIdx.x == 0) {
        int t = threadIdx.x;
        if (t < M_SEG) g_cnt[t] = 0.f;
        __syncthreads();
        int r0 = t * 256;
        int cur = vidx[r0];
        float acc = 0.f;
        for (int r = r0; r < r0 + 256; r++) {
            int s = vidx[r];
            if (s != cur) { atomicAdd(&g_cnt[cur], acc); acc = 0.f; cur = s; }
            acc += 1.f;
        }
        atomicAdd(&g_cnt[cur], acc);
    } else {
        int i = (blockIdx.x - 1) * 256 + threadIdx.x;
        if (i < V_N) g_deg[i] = 0;
        if (i < M_SEG * 1024) g_pooled[i] = 0.f;
        if (i < 1792) { g_colsum[i] = 0.f; g_colsq[i] = 0.f; }
    }
}

// ---------------- CSR build ----------------
__global__ void k_count(const int* __restrict__ edges) {
    int e = blockIdx.x * blockDim.x + threadIdx.x;
    if (e < E_N) {
        atomicAdd(&g_deg[edges[2 * e]], 1);
        atomicAdd(&g_deg[edges[2 * e + 1]], 1);
    }
}

__global__ void k_scan() {
    __shared__ int s[1024];
    int tid = threadIdx.x;
    int base = tid * 64;
    int sum = 0;
#pragma unroll
    for (int i = 0; i < 64; i++) sum += g_deg[base + i];
    s[tid] = sum;
    __syncthreads();
    for (int off = 1; off < 1024; off <<= 1) {
        int v = (tid >= off) ? s[tid - off] : 0;
        __syncthreads();
        s[tid] += v;
        __syncthreads();
    }
    int run = s[tid] - sum;
    for (int i = 0; i < 64; i++) {
        g_off[base + i] = run;
        g_pos[base + i] = run;
        run += g_deg[base + i];
    }
    if (tid == 1023) g_off[V_N] = run;
}

__global__ void k_fill(const int* __restrict__ edges) {
    int e = blockIdx.x * blockDim.x + threadIdx.x;
    if (e < E_N) {
        int i = edges[2 * e];
        int j = edges[2 * e + 1];
        int p = atomicAdd(&g_pos[i], 1); g_adj[p] = j;
        int q = atomicAdd(&g_pos[j], 1); g_adj[q] = i;
    }
}

// ---------------- weight transpose fp16 ----------------
__global__ void k_wprep_all(const float* __restrict__ w0_1, const float* __restrict__ w1_1,
                            const float* __restrict__ w0_2, const float* __restrict__ w1_2) {
    int idx = blockIdx.x * blockDim.x + threadIdx.x;
    if (idx < 262144) {
        int n = idx >> 9;
        int k = idx & 511;
        float v = (k < 256) ? w0_1[(size_t)k * 512 + n]
                            : w1_1[(size_t)(k - 256) * 512 + n];
        g_wt2[idx] = __float2half_rn(v);
    } else {
        int j = idx - 262144;
        if (j < 1048576) {
            int n = j >> 10;
            int k = j & 1023;
            float v = (k < 512) ? w0_2[(size_t)k * 1024 + n]
                                : w1_2[(size_t)(k - 512) * 1024 + n];
            g_wt3[j] = __float2half_rn(v);
        }
    }
}

// ---------------- layer-1 gather ----------------
__global__ void k_gather_small(const float* __restrict__ verts) {
    int v = blockIdx.x * blockDim.x + threadIdx.x;
    if (v >= V_N) return;
    int s = g_off[v], e = g_off[v + 1];
    float a0 = 0.f, a1 = 0.f, a2 = 0.f;
    for (int k = s; k < e; k++) {
        int u = g_adj[k];
        a0 += verts[u * 3 + 0];
        a1 += verts[u * 3 + 1];
        a2 += verts[u * 3 + 2];
    }
    g_y[v * 3 + 0] = a0;
    g_y[v * 3 + 1] = a1;
    g_y[v * 3 + 2] = a2;
}

// ---------------- layer-1 fully fused ----------------
__global__ __launch_bounds__(256) void k_l1fused(
    const float* __restrict__ verts,
    const float* __restrict__ w0, const float* __restrict__ b0,
    const float* __restrict__ w1, const float* __restrict__ b1) {
    __shared__ float sx[128][3], sy[128][3], sdeg[128];
    int v0 = blockIdx.x * 128;
    int tid = threadIdx.x;
    for (int i = tid; i < 384; i += 256) {
        sx[i / 3][i % 3] = verts[v0 * 3 + i];
        sy[i / 3][i % 3] = g_y[v0 * 3 + i];
    }
    if (tid < 128) sdeg[tid] = (float)g_deg[v0 + tid];
    __syncthreads();

    int c = (tid & 127) * 2;
    int vh = (tid >> 7) * 64;
    float wa0 = w0[0 * 256 + c], wa1 = w0[1 * 256 + c], wa2 = w0[2 * 256 + c];
    float wb0 = w0[0 * 256 + c + 1], wb1 = w0[1 * 256 + c + 1], wb2 = w0[2 * 256 + c + 1];
    float va0 = w1[0 * 256 + c], va1 = w1[1 * 256 + c], va2 = w1[2 * 256 + c];
    float vb0 = w1[0 * 256 + c + 1], vb1 = w1[1 * 256 + c + 1], vb2 = w1[2 * 256 + c + 1];
    float b0a = b0[c], b0b = b0[c + 1], b1a = b1[c], b1b = b1[c + 1];

    float s0 = 0.f, s1 = 0.f, q0 = 0.f, q1 = 0.f;
#pragma unroll 4
    for (int i = 0; i < 64; i++) {
        int v = vh + i;
        float x0 = sx[v][0], x1 = sx[v][1], x2 = sx[v][2];
        float y0 = sy[v][0], y1 = sy[v][1], y2 = sy[v][2];
        float dg = sdeg[v];
        float z0 = x0 * wa0 + x1 * wa1 + x2 * wa2
                 + y0 * va0 + y1 * va1 + y2 * va2 + b0a + dg * b1a;
        float z1 = x0 * wb0 + x1 * wb1 + x2 * wb2
                 + y0 * vb0 + y1 * vb1 + y2 * vb2 + b0b + dg * b1b;
        *(__half2*)&g_zh[(size_t)(v0 + v) * 256 + c] = __floats2half2_rn(z0, z1);
        s0 += z0; s1 += z1;
        q0 += z0 * z0; q1 += z1 * z1;
    }
    atomicAdd(&g_colsum[c], s0);
    atomicAdd(&g_colsum[c + 1], s1);
    atomicAdd(&g_colsq[c], q0);
    atomicAdd(&g_colsq[c + 1], q1);
}

// ---------------- fp16 gathers ----------------
__device__ __forceinline__ void acc_u4(float2* a, uint4 t) {
    __half2* h = (__half2*)&t;
#pragma unroll
    for (int i = 0; i < 4; i++) {
        float2 f = __half22float2(h[i]);
        a[i].x += f.x; a[i].y += f.y;
    }
}
__device__ __forceinline__ uint4 pack_u4(const float2* a) {
    uint4 o;
    __half2* oh = (__half2*)&o;
#pragma unroll
    for (int i = 0; i < 4; i++) oh[i] = __floats2half2_rn(a[i].x, a[i].y);
    return o;
}

__global__ void k_gather_h256() {
    int gw = (blockIdx.x * blockDim.x + threadIdx.x) >> 5;
    int lane = threadIdx.x & 31;
    if (gw >= V_N) return;
    int s = g_off[gw], e = g_off[gw + 1];
    const __half* xb = g_xh + lane * 8;
    float2 a[4];
#pragma unroll
    for (int i = 0; i < 4; i++) a[i] = make_float2(0.f, 0.f);
    int k = s;
    for (; k + 2 <= e; k += 2) {
        int u0 = g_adj[k], u1 = g_adj[k + 1];
        uint4 t0 = *(const uint4*)(xb + (size_t)u0 * 256);
        uint4 t1 = *(const uint4*)(xb + (size_t)u1 * 256);
        acc_u4(a, t0);
        acc_u4(a, t1);
    }
    if (k < e) {
        int u = g_adj[k];
        acc_u4(a, *(const uint4*)(xb + (size_t)u * 256));
    }
    *(uint4*)(g_yh + (size_t)gw * 256 + lane * 8) = pack_u4(a);
}

__global__ void k_gather_h512() {
    int gw = (blockIdx.x * blockDim.x + threadIdx.x) >> 5;
    int lane = threadIdx.x & 31;
    if (gw >= V_N) return;
    int s = g_off[gw], e = g_off[gw + 1];
    const __half* xb0 = g_xh + lane * 8;
    const __half* xb1 = g_xh + (lane + 32) * 8;
    float2 a0[4], a1[4];
#pragma unroll
    for (int i = 0; i < 4; i++) { a0[i] = make_float2(0.f, 0.f); a1[i] = make_float2(0.f, 0.f); }
    int k = s;
    for (; k + 2 <= e; k += 2) {
        int u0 = g_adj[k], u1 = g_adj[k + 1];
        size_t r0 = (size_t)u0 * 512, r1 = (size_t)u1 * 512;
        uint4 t00 = *(const uint4*)(xb0 + r0);
        uint4 t01 = *(const uint4*)(xb1 + r0);
        uint4 t10 = *(const uint4*)(xb0 + r1);
        uint4 t11 = *(const uint4*)(xb1 + r1);
        acc_u4(a0, t00); acc_u4(a1, t01);
        acc_u4(a0, t10); acc_u4(a1, t11);
    }
    if (k < e) {
        size_t r = (size_t)g_adj[k] * 512;
        acc_u4(a0, *(const uint4*)(xb0 + r));
        acc_u4(a1, *(const uint4*)(xb1 + r));
    }
    __half* yb = g_yh + (size_t)gw * 512;
    *(uint4*)(yb + lane * 8) = pack_u4(a0);
    *(uint4*)(yb + (lane + 32) * 8) = pack_u4(a1);
}

// ---------------- fp16 tensor GEMM ----------------
#define TILE_B   10240
#define STAGE_B  (2 * TILE_B)
#define GSMEM    (2 * STAGE_B + 1024)

__global__ __launch_bounds__(256, 2) void k_gemm_mma(
    int wsel,
    const float* __restrict__ b0v, const float* __restrict__ b1v,
    int K, int Dout, int cbase)
{
    extern __shared__ char dynsm[];
    float* s_sum = (float*)(dynsm + 2 * STAGE_B);
    float* s_sq  = s_sum + 128;

    const __half* Wt = wsel ? g_wt3 : g_wt2;

    int tid = threadIdx.x, wid = tid >> 5, lane = tid & 31;
    int m0 = blockIdx.y * 128, n0 = blockIdx.x * 128;
    int wm = (wid & 3) * 32, wn = (wid >> 2) * 64;

    if (tid < 128) { s_sum[tid] = 0.f; s_sq[tid] = 0.f; }

    float acc[2][8][4];
#pragma unroll
    for (int a = 0; a < 2; a++)
#pragma unroll
        for (int b = 0; b < 8; b++)
#pragma unroll
            for (int c = 0; c < 4; c++) acc[a][b][c] = 0.f;

    int K2 = 2 * K, nkt = K2 >> 5, ktx = K >> 5;

    auto load_stage = [&](int stage, int kt) {
        const __half* Ah_;
        int kc;
        if (kt < ktx) { Ah_ = g_xh; kc = kt << 5; }
        else          { Ah_ = g_yh; kc = (kt - ktx) << 5; }
        int gk = kt << 5;
        char* base = dynsm + stage * STAGE_B;
#pragma unroll
        for (int i = 0; i < 4; i++) {
            int idx = tid + i * 256;
            int arr = idx >> 9;
            int v = idx & 511;
            int r = v >> 2;
            int cs = (v & 3) * 8;
            uint32_t so = smem_u32(base + arr * TILE_B + r * 80 + cs * 2);
            const __half* g;
            if (arr == 0) g = Ah_ + (size_t)(m0 + r) * K + kc + cs;
            else          g = Wt + (size_t)(n0 + r) * K2 + gk + cs;
            CP16(so, g);
        }
    };

    load_stage(0, 0);
    CP_COMMIT();

    for (int kt = 0; kt < nkt; ++kt) {
        if (kt + 1 < nkt) {
            load_stage((kt + 1) & 1, kt + 1);
            CP_COMMIT();
            CP_WAIT1();
        } else {
            CP_WAIT0();
        }
        __syncthreads();

        uint32_t aAh = smem_u32(dynsm + (kt & 1) * STAGE_B);
        uint32_t aBh = aAh + TILE_B;

#pragma unroll
        for (int k16 = 0; k16 < 2; k16++) {
            int kk = k16 * 16;
            uint32_t ah[2][4];
#pragma unroll
            for (int mi = 0; mi < 2; mi++) {
                int ar = wm + mi * 16 + (lane & 15);
                int ac = kk + (lane >> 4) * 8;
                LDSM_X4(ah[mi], aAh + ar * 80 + ac * 2);
            }
            int gq = lane >> 3;
            int brb = wn + ((gq >> 1) & 1) * 8 + (lane & 7);
            int bcb = kk + (gq & 1) * 8;
#pragma unroll
            for (int ni = 0; ni < 8; ni += 2) {
                uint32_t b4[4];
                LDSM_X4(b4, aBh + (brb + ni * 8) * 80 + bcb * 2);
#pragma unroll
                for (int mi = 0; mi < 2; mi++) {
                    MMA16816H(acc[mi][ni], ah[mi], b4);
                    MMA16816H(acc[mi][ni + 1], ah[mi], b4 + 2);
                }
            }
        }
        __syncthreads();
    }

    float ls0[8], ls1[8], lq0[8], lq1[8];
#pragma unroll
    for (int ni = 0; ni < 8; ni++) { ls0[ni] = ls1[ni] = lq0[ni] = lq1[ni] = 0.f; }

    int r0 = lane >> 2, c0 = (lane & 3) * 2;
#pragma unroll
    for (int mi = 0; mi < 2; mi++) {
        int mA = m0 + wm + mi * 16 + r0;
        float dgA = (float)g_deg[mA];
        float dgB = (float)g_deg[mA + 8];
#pragma unroll
        for (int ni = 0; ni < 8; ni++) {
            int n = n0 + wn + ni * 8 + c0;
            float b00 = b0v[n], b01 = b0v[n + 1];
            float b10 = b1v[n], b11 = b1v[n + 1];
            float2 o0, o1;
            o0.x = acc[mi][ni][0] + b00 + dgA * b10;
            o0.y = acc[mi][ni][1] + b01 + dgA * b11;
            o1.x = acc[mi][ni][2] + b00 + dgB * b10;
            o1.y = acc[mi][ni][3] + b01 + dgB * b11;
            *(__half2*)&g_zh[(size_t)mA * Dout + n] = __floats2half2_rn(o0.x, o0.y);
            *(__half2*)&g_zh[(size_t)(mA + 8) * Dout + n] = __floats2half2_rn(o1.x, o1.y);
            ls0[ni] += o0.x + o1.x;
            ls1[ni] += o0.y + o1.y;
            lq0[ni] += o0.x * o0.x + o1.x * o1.x;
            lq1[ni] += o0.y * o0.y + o1.y * o1.y;
        }
    }
#pragma unroll
    for (int ni = 0; ni < 8; ni++) {
#pragma unroll
        for (int off = 4; off < 32; off <<= 1) {
            ls0[ni] += __shfl_xor_sync(0xffffffffu, ls0[ni], off);
            ls1[ni] += __shfl_xor_sync(0xffffffffu, ls1[ni], off);
            lq0[ni] += __shfl_xor_sync(0xffffffffu, lq0[ni], off);
            lq1[ni] += __shfl_xor_sync(0xffffffffu, lq1[ni], off);
        }
    }
    if (lane < 4) {
#pragma unroll
        for (int ni = 0; ni < 8; ni++) {
            int col = wn + ni * 8 + lane * 2;
            atomicAdd(&s_sum[col], ls0[ni]);
            atomicAdd(&s_sum[col + 1], ls1[ni]);
            atomicAdd(&s_sq[col], lq0[ni]);
            atomicAdd(&s_sq[col + 1], lq1[ni]);
        }
    }
    __syncthreads();
    if (tid < 128) {
        atomicAdd(&g_colsum[cbase + n0 + tid], s_sum[tid]);
        atomicAdd(&g_colsq[cbase + n0 + tid], s_sq[tid]);
    }
}

// ---------------- BN+ReLU ----------------
__global__ void k_bnrelu_h(const float* __restrict__ gamma,
                           const float* __restrict__ beta, int Dout, int cbase) {
    int i2 = blockIdx.x * blockDim.x + threadIdx.x;
    int idx = i2 * 2;
    int c = idx % Dout;
    const float invV = 1.f / (float)V_N;
    float mu0 = g_colsum[cbase + c] * invV;
    float mu1 = g_colsum[cbase + c + 1] * invV;
    float v0 = g_colsq[cbase + c] * invV - mu0 * mu0;
    float v1 = g_colsq[cbase + c + 1] * invV - mu1 * mu1;
    float2 z = __half22float2(*(__half2*)&g_zh[idx]);
    float r0 = fmaxf(gamma[c] * (z.x - mu0) * rsqrtf(v0 + EPS_BN) + beta[c], 0.f);
    float r1 = fmaxf(gamma[c + 1] * (z.y - mu1) * rsqrtf(v1 + EPS_BN) + beta[c + 1], 0.f);
    *(__half2*)&g_xh[idx] = __floats2half2_rn(r0, r1);
}

// ---------------- layer-3 fused BN+ReLU+pool ----------------
__global__ void k_bnrelu_pool(const float* __restrict__ gamma,
                              const float* __restrict__ beta,
                              const int* __restrict__ vidx, int Dout, int cbase) {
    int c = blockIdx.x * blockDim.x + threadIdx.x;
    int r0 = blockIdx.y * 1024;
    const float invV = 1.f / (float)V_N;
    float mu = g_colsum[cbase + c] * invV;
    float var = g_colsq[cbase + c] * invV - mu * mu;
    float sc = gamma[c] * rsqrtf(var + EPS_BN);
    float be = beta[c];
    int cur = vidx[r0];
    float acc = 0.f;
    for (int r = r0; r < r0 + 1024; r++) {
        int s = vidx[r];
        if (s != cur) { atomicAdd(&g_pooled[(size_t)cur * Dout + c], acc); acc = 0.f; cur = s; }
        float z = __half2float(g_zh[(size_t)r * Dout + c]);
        acc += fmaxf(sc * (z - mu) + be, 0.f);
    }
    atomicAdd(&g_pooled[(size_t)cur * Dout + c], acc);
}

// ---------------- FC1 + heads ----------------
__global__ void k_fc1(const float* __restrict__ fw, const float* __restrict__ fb) {
    __shared__ float sp[1024];
    int m = blockIdx.x;
    float inv = 1.f / fmaxf(g_cnt[m], 1.f);
    for (int i = threadIdx.x; i < 1024; i += 128)
        sp[i] = g_pooled[m * 1024 + i] * inv;
    __syncthreads();
    float s = fb[threadIdx.x];
    for (int k = 0; k < 1024; k++) s += sp[k] * fw[k * 128 + threadIdx.x];
    g_h[m * 128 + threadIdx.x] = fmaxf(s, 0.f);
}

__global__ void k_heads(const float* __restrict__ sw, const float* __restrict__ sb,
                        const float* __restrict__ mw, const float* __restrict__ mb,
                        const float* __restrict__ fw, const float* __restrict__ fb,
                        const float* __restrict__ aw, const float* __restrict__ ab,
                        float* __restrict__ out) {
    int t = threadIdx.x;
    const float* w; const float* b; int C, base;
    if (t < 192)       { w = sw; b = sb; C = 3; base = 0; }
    else if (t < 320)  { w = mw; b = mb; C = 2; base = 192; }
    else if (t < 576)  { w = fw; b = fb; C = 4; base = 320; }
    else               { w = aw; b = ab; C = 5; base = 576; }
    int lo = t - base;
    int m = lo / C, c = lo % C;
    float s = b[c];
    for (int k = 0; k < 128; k++) s += g_h[m * 128 + k] * w[k * C + c];
    out[t] = s;
}

// ---------------- launch orchestration ----------------
extern "C" void kernel_launch(void* const* d_in, const int* in_sizes, int n_in,
                              void* d_out, int out_size) {
    const float* verts = (const float*)d_in[0];
    const int* edges = (const int*)d_in[1];
    const int* vidx = (const int*)d_in[2];
    const float* w0_0 = (const float*)d_in[3];
    const float* b0_0 = (const float*)d_in[4];
    const float* w1_0 = (const float*)d_in[5];
    const float* b1_0 = (const float*)d_in[6];
    const float* g_0 = (const float*)d_in[7];
    const float* be_0 = (const float*)d_in[8];
    const float* w0_1 = (const float*)d_in[9];
    const float* b0_1 = (const float*)d_in[10];
    const float* w1_1 = (const float*)d_in[11];
    const float* b1_1 = (const float*)d_in[12];
    const float* g_1 = (const float*)d_in[13];
    const float* be_1 = (const float*)d_in[14];
    const float* w0_2 = (const float*)d_in[15];
    const float* b0_2 = (const float*)d_in[16];
    const float* w1_2 = (const float*)d_in[17];
    const float* b1_2 = (const float*)d_in[18];
    const float* g_2 = (const float*)d_in[19];
    const float* be_2 = (const float*)d_in[20];
    const float* fc1_w = (const float*)d_in[21];
    const float* fc1_b = (const float*)d_in[22];
    const float* style_w = (const float*)d_in[23];
    const float* style_b = (const float*)d_in[24];
    const float* sem_w = (const float*)d_in[25];
    const float* sem_b = (const float*)d_in[26];
    const float* fun_w = (const float*)d_in[27];
    const float* fun_b = (const float*)d_in[28];
    const float* aes_w = (const float*)d_in[29];
    const float* aes_b = (const float*)d_in[30];

    cudaFuncSetAttribute(k_gemm_mma, cudaFuncAttributeMaxDynamicSharedMemorySize,
                         GSMEM);

    k_stamp<<<1, 1>>>(0);
    // init + CSR build + weight prep
    k_init<<<257, 256>>>(vidx);
    k_count<<<E_N / 256, 256>>>(edges);
    k_scan<<<1, 1024>>>();
    k_fill<<<E_N / 256, 256>>>(edges);
    k_wprep_all<<<(1310720 + 255) / 256, 256>>>(w0_1, w1_1, w0_2, w1_2);
    k_stamp<<<1, 1>>>(1);

    // layer 1
    k_gather_small<<<V_N / 256, 256>>>(verts);
    k_stamp<<<1, 1>>>(2);
    k_l1fused<<<V_N / 128, 256>>>(verts, w0_0, b0_0, w1_0, b1_0);
    k_stamp<<<1, 1>>>(3);
    k_bnrelu_h<<<(V_N * 256 / 2) / 256, 256>>>(g_0, be_0, 256, 0);
    k_stamp<<<1, 1>>>(4);

    // layer 2
    k_gather_h256<<<V_N / 8, 256>>>();
    k_stamp<<<1, 1>>>(5);
    {
        dim3 grid(512 / 128, V_N / 128);
        k_gemm_mma<<<grid, 256, GSMEM>>>(0, b0_1, b1_1, 256, 512, 256);
    }
    k_stamp<<<1, 1>>>(6);
    k_bnrelu_h<<<(V_N * 512 / 2) / 256, 256>>>(g_1, be_1, 512, 256);
    k_stamp<<<1, 1>>>(7);

    // layer 3
    k_gather_h512<<<V_N / 8, 256>>>();
    k_stamp<<<1, 1>>>(8);
    {
        dim3 grid(1024 / 128, V_N / 128);
        k_gemm_mma<<<grid, 256, GSMEM>>>(1, b0_2, b1_2, 512, 1024, 768);
    }
    k_stamp<<<1, 1>>>(9);
    k_bnrelu_pool<<<dim3(1024 / 256, V_N / 1024), 256>>>(g_2, be_2, vidx, 1024, 768);
    k_stamp<<<1, 1>>>(10);

    // FC1 + 4 heads
    k_fc1<<<M_SEG, 128>>>(fc1_w, fc1_b);
    k_heads<<<1, 896>>>(style_w, style_b, sem_w, sem_b, fun_w, fun_b,
                        aes_w, aes_b, (float*)d_out);
    k_stamp<<<1, 1>>>(11);
    k_report<<<1, 1>>>(12);
}

// round 14
// speedup vs baseline: 1.3250x; 1.3250x over previous
#include <cuda_runtime.h>
#include <cuda_fp16.h>
#include <cstdint>

#define V_N 65536
#define E_N 196608
#define M_SEG 64
#define NN1 128
#define EPS_BN 1e-5f

// ---------------- device scratch (no allocations allowed) ----------------
__device__ float g_y[262144];      // layer-1 gathered feats (V*3)
__device__ __half g_zh[67108864];  // gemm output fp16, up to V*1024
__device__ __half g_xh[33554432];  // activation fp16, V*512 max
__device__ __half g_yh[33554432];  // gathered fp16
__device__ __half g_wt2[262144];   // layer-2 weights [512][512] fp16
__device__ __half g_wt3[1048576];  // layer-3 weights [1024][1024] fp16
__device__ int   g_deg[V_N];
__device__ int   g_off[V_N + 1];
__device__ int   g_pos[V_N];
__device__ int   g_adj[2 * E_N];
__device__ int   g_part[256];
__device__ int   g_partoff[256];
__device__ float g_colsum[1792];   // per-layer regions: L1 @0, L2 @256, L3 @768
__device__ float g_colsq[1792];
__device__ float g_pooled[M_SEG * 1024];
__device__ float g_cnt[M_SEG];
__device__ float g_h[M_SEG * NN1];

// ---------------- PTX helpers ----------------
__device__ __forceinline__ uint32_t smem_u32(const void* p) {
    uint32_t a;
    asm("{ .reg .u64 t; cvta.to.shared.u64 t, %1; cvt.u32.u64 %0, t; }"
        : "=r"(a) : "l"(p));
    return a;
}

#define LDSM_X4(r, addr) \
    asm volatile("ldmatrix.sync.aligned.m8n8.x4.shared.b16 {%0,%1,%2,%3}, [%4];" \
                 : "=r"((r)[0]), "=r"((r)[1]), "=r"((r)[2]), "=r"((r)[3]) : "r"(addr))

#define MMA16816H(d, a, b) \
    asm volatile("mma.sync.aligned.m16n8k16.row.col.f32.f16.f16.f32 " \
                 "{%0,%1,%2,%3}, {%4,%5,%6,%7}, {%8,%9}, {%0,%1,%2,%3};" \
                 : "+f"((d)[0]), "+f"((d)[1]), "+f"((d)[2]), "+f"((d)[3]) \
                 : "r"((a)[0]), "r"((a)[1]), "r"((a)[2]), "r"((a)[3]), \
                   "r"((b)[0]), "r"((b)[1]))

#define CP16(saddr, gptr) \
    asm volatile("cp.async.cg.shared.global [%0], [%1], 16;" \
                 :: "r"(saddr), "l"(gptr) : "memory")
#define CP_COMMIT() asm volatile("cp.async.commit_group;" ::: "memory")
#define CP_WAIT1()  asm volatile("cp.async.wait_group 1;" ::: "memory")
#define CP_WAIT0()  asm volatile("cp.async.wait_group 0;" ::: "memory")

// ---------------- fused init ----------------
__global__ void k_init(const int* __restrict__ vidx) {
    if (blockIdx.x == 0) {
        int t = threadIdx.x;
        if (t < M_SEG) g_cnt[t] = 0.f;
        __syncthreads();
        int r0 = t * 256;
        int cur = vidx[r0];
        float acc = 0.f;
        for (int r = r0; r < r0 + 256; r++) {
            int s = vidx[r];
            if (s != cur) { atomicAdd(&g_cnt[cur], acc); acc = 0.f; cur = s; }
            acc += 1.f;
        }
        atomicAdd(&g_cnt[cur], acc);
    } else {
        int i = (blockIdx.x - 1) * 256 + threadIdx.x;
        if (i < V_N) g_deg[i] = 0;
        if (i < M_SEG * 1024) g_pooled[i] = 0.f;
        if (i < 1792) { g_colsum[i] = 0.f; g_colsq[i] = 0.f; }
    }
}

// ---------------- CSR build ----------------
__global__ void k_count(const int* __restrict__ edges) {
    int e = blockIdx.x * blockDim.x + threadIdx.x;
    if (e < E_N) {
        atomicAdd(&g_deg[edges[2 * e]], 1);
        atomicAdd(&g_deg[edges[2 * e + 1]], 1);
    }
}

// hierarchical exclusive scan over g_deg (65536 = 256 blocks x 256)
__global__ void k_scan_part() {
    __shared__ int s[256];
    int i = blockIdx.x * 256 + threadIdx.x;
    s[threadIdx.x] = g_deg[i];
    __syncthreads();
    for (int off = 128; off > 0; off >>= 1) {
        if (threadIdx.x < off) s[threadIdx.x] += s[threadIdx.x + off];
        __syncthreads();
    }
    if (threadIdx.x == 0) g_part[blockIdx.x] = s[0];
}

__global__ void k_scan_top() {
    __shared__ int s[256];
    int t = threadIdx.x;
    int v = g_part[t];
    s[t] = v;
    __syncthreads();
    for (int off = 1; off < 256; off <<= 1) {
        int u = (t >= off) ? s[t - off] : 0;
        __syncthreads();
        s[t] += u;
        __syncthreads();
    }
    g_partoff[t] = s[t] - v;   // exclusive prefix of block sums
    if (t == 255) g_off[V_N] = s[255];
}

__global__ void k_scan_apply() {
    __shared__ int s[256];
    int i = blockIdx.x * 256 + threadIdx.x;
    int d = g_deg[i];
    s[threadIdx.x] = d;
    __syncthreads();
    for (int off = 1; off < 256; off <<= 1) {
        int u = (threadIdx.x >= off) ? s[threadIdx.x - off] : 0;
        __syncthreads();
        s[threadIdx.x] += u;
        __syncthreads();
    }
    int excl = s[threadIdx.x] - d + g_partoff[blockIdx.x];
    g_off[i] = excl;
    g_pos[i] = excl;
}

__global__ void k_fill(const int* __restrict__ edges) {
    int e = blockIdx.x * blockDim.x + threadIdx.x;
    if (e < E_N) {
        int i = edges[2 * e];
        int j = edges[2 * e + 1];
        int p = atomicAdd(&g_pos[i], 1); g_adj[p] = j;
        int q = atomicAdd(&g_pos[j], 1); g_adj[q] = i;
    }
}

// ---------------- weight transpose fp16 ----------------
__global__ void k_wprep_all(const float* __restrict__ w0_1, const float* __restrict__ w1_1,
                            const float* __restrict__ w0_2, const float* __restrict__ w1_2) {
    int idx = blockIdx.x * blockDim.x + threadIdx.x;
    if (idx < 262144) {
        int n = idx >> 9;
        int k = idx & 511;
        float v = (k < 256) ? w0_1[(size_t)k * 512 + n]
                            : w1_1[(size_t)(k - 256) * 512 + n];
        g_wt2[idx] = __float2half_rn(v);
    } else {
        int j = idx - 262144;
        if (j < 1048576) {
            int n = j >> 10;
            int k = j & 1023;
            float v = (k < 512) ? w0_2[(size_t)k * 1024 + n]
                                : w1_2[(size_t)(k - 512) * 1024 + n];
            g_wt3[j] = __float2half_rn(v);
        }
    }
}

// ---------------- layer-1 gather ----------------
__global__ void k_gather_small(const float* __restrict__ verts) {
    int v = blockIdx.x * blockDim.x + threadIdx.x;
    if (v >= V_N) return;
    int s = g_off[v], e = g_off[v + 1];
    float a0 = 0.f, a1 = 0.f, a2 = 0.f;
    for (int k = s; k < e; k++) {
        int u = g_adj[k];
        a0 += verts[u * 3 + 0];
        a1 += verts[u * 3 + 1];
        a2 += verts[u * 3 + 2];
    }
    g_y[v * 3 + 0] = a0;
    g_y[v * 3 + 1] = a1;
    g_y[v * 3 + 2] = a2;
}

// ---------------- layer-1 fully fused ----------------
__global__ __launch_bounds__(256) void k_l1fused(
    const float* __restrict__ verts,
    const float* __restrict__ w0, const float* __restrict__ b0,
    const float* __restrict__ w1, const float* __restrict__ b1) {
    __shared__ float sx[128][3], sy[128][3], sdeg[128];
    int v0 = blockIdx.x * 128;
    int tid = threadIdx.x;
    for (int i = tid; i < 384; i += 256) {
        sx[i / 3][i % 3] = verts[v0 * 3 + i];
        sy[i / 3][i % 3] = g_y[v0 * 3 + i];
    }
    if (tid < 128) sdeg[tid] = (float)g_deg[v0 + tid];
    __syncthreads();

    int c = (tid & 127) * 2;
    int vh = (tid >> 7) * 64;
    float wa0 = w0[0 * 256 + c], wa1 = w0[1 * 256 + c], wa2 = w0[2 * 256 + c];
    float wb0 = w0[0 * 256 + c + 1], wb1 = w0[1 * 256 + c + 1], wb2 = w0[2 * 256 + c + 1];
    float va0 = w1[0 * 256 + c], va1 = w1[1 * 256 + c], va2 = w1[2 * 256 + c];
    float vb0 = w1[0 * 256 + c + 1], vb1 = w1[1 * 256 + c + 1], vb2 = w1[2 * 256 + c + 1];
    float b0a = b0[c], b0b = b0[c + 1], b1a = b1[c], b1b = b1[c + 1];

    float s0 = 0.f, s1 = 0.f, q0 = 0.f, q1 = 0.f;
#pragma unroll 4
    for (int i = 0; i < 64; i++) {
        int v = vh + i;
        float x0 = sx[v][0], x1 = sx[v][1], x2 = sx[v][2];
        float y0 = sy[v][0], y1 = sy[v][1], y2 = sy[v][2];
        float dg = sdeg[v];
        float z0 = x0 * wa0 + x1 * wa1 + x2 * wa2
                 + y0 * va0 + y1 * va1 + y2 * va2 + b0a + dg * b1a;
        float z1 = x0 * wb0 + x1 * wb1 + x2 * wb2
                 + y0 * vb0 + y1 * vb1 + y2 * vb2 + b0b + dg * b1b;
        *(__half2*)&g_zh[(size_t)(v0 + v) * 256 + c] = __floats2half2_rn(z0, z1);
        s0 += z0; s1 += z1;
        q0 += z0 * z0; q1 += z1 * z1;
    }
    atomicAdd(&g_colsum[c], s0);
    atomicAdd(&g_colsum[c + 1], s1);
    atomicAdd(&g_colsq[c], q0);
    atomicAdd(&g_colsq[c + 1], q1);
}

// ---------------- fp16 gathers ----------------
__device__ __forceinline__ void acc_u4(float2* a, uint4 t) {
    __half2* h = (__half2*)&t;
#pragma unroll
    for (int i = 0; i < 4; i++) {
        float2 f = __half22float2(h[i]);
        a[i].x += f.x; a[i].y += f.y;
    }
}
__device__ __forceinline__ uint4 pack_u4(const float2* a) {
    uint4 o;
    __half2* oh = (__half2*)&o;
#pragma unroll
    for (int i = 0; i < 4; i++) oh[i] = __floats2half2_rn(a[i].x, a[i].y);
    return o;
}

__global__ void k_gather_h256() {
    int gw = (blockIdx.x * blockDim.x + threadIdx.x) >> 5;
    int lane = threadIdx.x & 31;
    if (gw >= V_N) return;
    int s = g_off[gw], e = g_off[gw + 1];
    const __half* xb = g_xh + lane * 8;
    float2 a[4];
#pragma unroll
    for (int i = 0; i < 4; i++) a[i] = make_float2(0.f, 0.f);
    int k = s;
    for (; k + 2 <= e; k += 2) {
        int u0 = g_adj[k], u1 = g_adj[k + 1];
        uint4 t0 = *(const uint4*)(xb + (size_t)u0 * 256);
        uint4 t1 = *(const uint4*)(xb + (size_t)u1 * 256);
        acc_u4(a, t0);
        acc_u4(a, t1);
    }
    if (k < e) {
        int u = g_adj[k];
        acc_u4(a, *(const uint4*)(xb + (size_t)u * 256));
    }
    *(uint4*)(g_yh + (size_t)gw * 256 + lane * 8) = pack_u4(a);
}

__global__ void k_gather_h512() {
    int gw = (blockIdx.x * blockDim.x + threadIdx.x) >> 5;
    int lane = threadIdx.x & 31;
    if (gw >= V_N) return;
    int s = g_off[gw], e = g_off[gw + 1];
    const __half* xb0 = g_xh + lane * 8;
    const __half* xb1 = g_xh + (lane + 32) * 8;
    float2 a0[4], a1[4];
#pragma unroll
    for (int i = 0; i < 4; i++) { a0[i] = make_float2(0.f, 0.f); a1[i] = make_float2(0.f, 0.f); }
    int k = s;
    for (; k + 2 <= e; k += 2) {
        int u0 = g_adj[k], u1 = g_adj[k + 1];
        size_t r0 = (size_t)u0 * 512, r1 = (size_t)u1 * 512;
        uint4 t00 = *(const uint4*)(xb0 + r0);
        uint4 t01 = *(const uint4*)(xb1 + r0);
        uint4 t10 = *(const uint4*)(xb0 + r1);
        uint4 t11 = *(const uint4*)(xb1 + r1);
        acc_u4(a0, t00); acc_u4(a1, t01);
        acc_u4(a0, t10); acc_u4(a1, t11);
    }
    if (k < e) {
        size_t r = (size_t)g_adj[k] * 512;
        acc_u4(a0, *(const uint4*)(xb0 + r));
        acc_u4(a1, *(const uint4*)(xb1 + r));
    }
    __half* yb = g_yh + (size_t)gw * 512;
    *(uint4*)(yb + lane * 8) = pack_u4(a0);
    *(uint4*)(yb + (lane + 32) * 8) = pack_u4(a1);
}

// ---------------- fp16 tensor GEMM ----------------
#define TILE_B   10240
#define STAGE_B  (2 * TILE_B)
#define GSMEM    (2 * STAGE_B + 1024)

__global__ __launch_bounds__(256, 2) void k_gemm_mma(
    int wsel,
    const float* __restrict__ b0v, const float* __restrict__ b1v,
    int K, int Dout, int cbase)
{
    extern __shared__ char dynsm[];
    float* s_sum = (float*)(dynsm + 2 * STAGE_B);
    float* s_sq  = s_sum + 128;

    const __half* Wt = wsel ? g_wt3 : g_wt2;

    int tid = threadIdx.x, wid = tid >> 5, lane = tid & 31;
    int m0 = blockIdx.y * 128, n0 = blockIdx.x * 128;
    int wm = (wid & 3) * 32, wn = (wid >> 2) * 64;

    if (tid < 128) { s_sum[tid] = 0.f; s_sq[tid] = 0.f; }

    float acc[2][8][4];
#pragma unroll
    for (int a = 0; a < 2; a++)
#pragma unroll
        for (int b = 0; b < 8; b++)
#pragma unroll
            for (int c = 0; c < 4; c++) acc[a][b][c] = 0.f;

    int K2 = 2 * K, nkt = K2 >> 5, ktx = K >> 5;

    auto load_stage = [&](int stage, int kt) {
        const __half* Ah_;
        int kc;
        if (kt < ktx) { Ah_ = g_xh; kc = kt << 5; }
        else          { Ah_ = g_yh; kc = (kt - ktx) << 5; }
        int gk = kt << 5;
        char* base = dynsm + stage * STAGE_B;
#pragma unroll
        for (int i = 0; i < 4; i++) {
            int idx = tid + i * 256;
            int arr = idx >> 9;
            int v = idx & 511;
            int r = v >> 2;
            int cs = (v & 3) * 8;
            uint32_t so = smem_u32(base + arr * TILE_B + r * 80 + cs * 2);
            const __half* g;
            if (arr == 0) g = Ah_ + (size_t)(m0 + r) * K + kc + cs;
            else          g = Wt + (size_t)(n0 + r) * K2 + gk + cs;
            CP16(so, g);
        }
    };

    load_stage(0, 0);
    CP_COMMIT();

    for (int kt = 0; kt < nkt; ++kt) {
        if (kt + 1 < nkt) {
            load_stage((kt + 1) & 1, kt + 1);
            CP_COMMIT();
            CP_WAIT1();
        } else {
            CP_WAIT0();
        }
        __syncthreads();

        uint32_t aAh = smem_u32(dynsm + (kt & 1) * STAGE_B);
        uint32_t aBh = aAh + TILE_B;

#pragma unroll
        for (int k16 = 0; k16 < 2; k16++) {
            int kk = k16 * 16;
            uint32_t ah[2][4];
#pragma unroll
            for (int mi = 0; mi < 2; mi++) {
                int ar = wm + mi * 16 + (lane & 15);
                int ac = kk + (lane >> 4) * 8;
                LDSM_X4(ah[mi], aAh + ar * 80 + ac * 2);
            }
            int gq = lane >> 3;
            int brb = wn + ((gq >> 1) & 1) * 8 + (lane & 7);
            int bcb = kk + (gq & 1) * 8;
#pragma unroll
            for (int ni = 0; ni < 8; ni += 2) {
                uint32_t b4[4];
                LDSM_X4(b4, aBh + (brb + ni * 8) * 80 + bcb * 2);
#pragma unroll
                for (int mi = 0; mi < 2; mi++) {
                    MMA16816H(acc[mi][ni], ah[mi], b4);
                    MMA16816H(acc[mi][ni + 1], ah[mi], b4 + 2);
                }
            }
        }
        __syncthreads();
    }

    float ls0[8], ls1[8], lq0[8], lq1[8];
#pragma unroll
    for (int ni = 0; ni < 8; ni++) { ls0[ni] = ls1[ni] = lq0[ni] = lq1[ni] = 0.f; }

    int r0 = lane >> 2, c0 = (lane & 3) * 2;
#pragma unroll
    for (int mi = 0; mi < 2; mi++) {
        int mA = m0 + wm + mi * 16 + r0;
        float dgA = (float)g_deg[mA];
        float dgB = (float)g_deg[mA + 8];
#pragma unroll
        for (int ni = 0; ni < 8; ni++) {
            int n = n0 + wn + ni * 8 + c0;
            float b00 = b0v[n], b01 = b0v[n + 1];
            float b10 = b1v[n], b11 = b1v[n + 1];
            float2 o0, o1;
            o0.x = acc[mi][ni][0] + b00 + dgA * b10;
            o0.y = acc[mi][ni][1] + b01 + dgA * b11;
            o1.x = acc[mi][ni][2] + b00 + dgB * b10;
            o1.y = acc[mi][ni][3] + b01 + dgB * b11;
            *(__half2*)&g_zh[(size_t)mA * Dout + n] = __floats2half2_rn(o0.x, o0.y);
            *(__half2*)&g_zh[(size_t)(mA + 8) * Dout + n] = __floats2half2_rn(o1.x, o1.y);
            ls0[ni] += o0.x + o1.x;
            ls1[ni] += o0.y + o1.y;
            lq0[ni] += o0.x * o0.x + o1.x * o1.x;
            lq1[ni] += o0.y * o0.y + o1.y * o1.y;
        }
    }
#pragma unroll
    for (int ni = 0; ni < 8; ni++) {
#pragma unroll
        for (int off = 4; off < 32; off <<= 1) {
            ls0[ni] += __shfl_xor_sync(0xffffffffu, ls0[ni], off);
            ls1[ni] += __shfl_xor_sync(0xffffffffu, ls1[ni], off);
            lq0[ni] += __shfl_xor_sync(0xffffffffu, lq0[ni], off);
            lq1[ni] += __shfl_xor_sync(0xffffffffu, lq1[ni], off);
        }
    }
    if (lane < 4) {
#pragma unroll
        for (int ni = 0; ni < 8; ni++) {
            int col = wn + ni * 8 + lane * 2;
            atomicAdd(&s_sum[col], ls0[ni]);
            atomicAdd(&s_sum[col + 1], ls1[ni]);
            atomicAdd(&s_sq[col], lq0[ni]);
            atomicAdd(&s_sq[col + 1], lq1[ni]);
        }
    }
    __syncthreads();
    if (tid < 128) {
        atomicAdd(&g_colsum[cbase + n0 + tid], s_sum[tid]);
        atomicAdd(&g_colsq[cbase + n0 + tid], s_sq[tid]);
    }
}

// ---------------- BN+ReLU ----------------
__global__ void k_bnrelu_h(const float* __restrict__ gamma,
                           const float* __restrict__ beta, int Dout, int cbase) {
    int i2 = blockIdx.x * blockDim.x + threadIdx.x;
    int idx = i2 * 2;
    int c = idx % Dout;
    const float invV = 1.f / (float)V_N;
    float mu0 = g_colsum[cbase + c] * invV;
    float mu1 = g_colsum[cbase + c + 1] * invV;
    float v0 = g_colsq[cbase + c] * invV - mu0 * mu0;
    float v1 = g_colsq[cbase + c + 1] * invV - mu1 * mu1;
    float2 z = __half22float2(*(__half2*)&g_zh[idx]);
    float r0 = fmaxf(gamma[c] * (z.x - mu0) * rsqrtf(v0 + EPS_BN) + beta[c], 0.f);
    float r1 = fmaxf(gamma[c + 1] * (z.y - mu1) * rsqrtf(v1 + EPS_BN) + beta[c + 1], 0.f);
    *(__half2*)&g_xh[idx] = __floats2half2_rn(r0, r1);
}

// ---------------- layer-3 fused BN+ReLU+pool ----------------
__global__ void k_bnrelu_pool(const float* __restrict__ gamma,
                              const float* __restrict__ beta,
                              const int* __restrict__ vidx, int Dout, int cbase) {
    int c = blockIdx.x * blockDim.x + threadIdx.x;
    int r0 = blockIdx.y * 1024;
    const float invV = 1.f / (float)V_N;
    float mu = g_colsum[cbase + c] * invV;
    float var = g_colsq[cbase + c] * invV - mu * mu;
    float sc = gamma[c] * rsqrtf(var + EPS_BN);
    float be = beta[c];
    int cur = vidx[r0];
    float acc = 0.f;
    for (int r = r0; r < r0 + 1024; r++) {
        int s = vidx[r];
        if (s != cur) { atomicAdd(&g_pooled[(size_t)cur * Dout + c], acc); acc = 0.f; cur = s; }
        float z = __half2float(g_zh[(size_t)r * Dout + c]);
        acc += fmaxf(sc * (z - mu) + be, 0.f);
    }
    atomicAdd(&g_pooled[(size_t)cur * Dout + c], acc);
}

// ---------------- FC1 + heads ----------------
__global__ void k_fc1(const float* __restrict__ fw, const float* __restrict__ fb) {
    __shared__ float sp[1024];
    int m = blockIdx.x;
    float inv = 1.f / fmaxf(g_cnt[m], 1.f);
    for (int i = threadIdx.x; i < 1024; i += 128)
        sp[i] = g_pooled[m * 1024 + i] * inv;
    __syncthreads();
    float s = fb[threadIdx.x];
    for (int k = 0; k < 1024; k++) s += sp[k] * fw[k * 128 + threadIdx.x];
    g_h[m * 128 + threadIdx.x] = fmaxf(s, 0.f);
}

__global__ void k_heads(const float* __restrict__ sw, const float* __restrict__ sb,
                        const float* __restrict__ mw, const float* __restrict__ mb,
                        const float* __restrict__ fw, const float* __restrict__ fb,
                        const float* __restrict__ aw, const float* __restrict__ ab,
                        float* __restrict__ out) {
    int t = threadIdx.x;
    const float* w; const float* b; int C, base;
    if (t < 192)       { w = sw; b = sb; C = 3; base = 0; }
    else if (t < 320)  { w = mw; b = mb; C = 2; base = 192; }
    else if (t < 576)  { w = fw; b = fb; C = 4; base = 320; }
    else               { w = aw; b = ab; C = 5; base = 576; }
    int lo = t - base;
    int m = lo / C, c = lo % C;
    float s = b[c];
    for (int k = 0; k < 128; k++) s += g_h[m * 128 + k] * w[k * C + c];
    out[t] = s;
}

// ---------------- launch orchestration ----------------
extern "C" void kernel_launch(void* const* d_in, const int* in_sizes, int n_in,
                              void* d_out, int out_size) {
    const float* verts = (const float*)d_in[0];
    const int* edges = (const int*)d_in[1];
    const int* vidx = (const int*)d_in[2];
    const float* w0_0 = (const float*)d_in[3];
    const float* b0_0 = (const float*)d_in[4];
    const float* w1_0 = (const float*)d_in[5];
    const float* b1_0 = (const float*)d_in[6];
    const float* g_0 = (const float*)d_in[7];
    const float* be_0 = (const float*)d_in[8];
    const float* w0_1 = (const float*)d_in[9];
    const float* b0_1 = (const float*)d_in[10];
    const float* w1_1 = (const float*)d_in[11];
    const float* b1_1 = (const float*)d_in[12];
    const float* g_1 = (const float*)d_in[13];
    const float* be_1 = (const float*)d_in[14];
    const float* w0_2 = (const float*)d_in[15];
    const float* b0_2 = (const float*)d_in[16];
    const float* w1_2 = (const float*)d_in[17];
    const float* b1_2 = (const float*)d_in[18];
    const float* g_2 = (const float*)d_in[19];
    const float* be_2 = (const float*)d_in[20];
    const float* fc1_w = (const float*)d_in[21];
    const float* fc1_b = (const float*)d_in[22];
    const float* style_w = (const float*)d_in[23];
    const float* style_b = (const float*)d_in[24];
    const float* sem_w = (const float*)d_in[25];
    const float* sem_b = (const float*)d_in[26];
    const float* fun_w = (const float*)d_in[27];
    const float* fun_b = (const float*)d_in[28];
    const float* aes_w = (const float*)d_in[29];
    const float* aes_b = (const float*)d_in[30];

    cudaFuncSetAttribute(k_gemm_mma, cudaFuncAttributeMaxDynamicSharedMemorySize,
                         GSMEM);

    // init + CSR build (parallel scan) + weight prep
    k_init<<<257, 256>>>(vidx);
    k_count<<<E_N / 256, 256>>>(edges);
    k_scan_part<<<256, 256>>>();
    k_scan_top<<<1, 256>>>();
    k_scan_apply<<<256, 256>>>();
    k_fill<<<E_N / 256, 256>>>(edges);
    k_wprep_all<<<(1310720 + 255) / 256, 256>>>(w0_1, w1_1, w0_2, w1_2);

    // layer 1
    k_gather_small<<<V_N / 256, 256>>>(verts);
    k_l1fused<<<V_N / 128, 256>>>(verts, w0_0, b0_0, w1_0, b1_0);
    k_bnrelu_h<<<(V_N * 256 / 2) / 256, 256>>>(g_0, be_0, 256, 0);

    // layer 2
    k_gather_h256<<<V_N / 8, 256>>>();
    {
        dim3 grid(512 / 128, V_N / 128);
        k_gemm_mma<<<grid, 256, GSMEM>>>(0, b0_1, b1_1, 256, 512, 256);
    }
    k_bnrelu_h<<<(V_N * 512 / 2) / 256, 256>>>(g_1, be_1, 512, 256);

    // layer 3
    k_gather_h512<<<V_N / 8, 256>>>();
    {
        dim3 grid(1024 / 128, V_N / 128);
        k_gemm_mma<<<grid, 256, GSMEM>>>(1, b0_2, b1_2, 512, 1024, 768);
    }
    k_bnrelu_pool<<<dim3(1024 / 256, V_N / 1024), 256>>>(g_2, be_2, vidx, 1024, 768);

    // FC1 + 4 heads
    k_fc1<<<M_SEG, 128>>>(fc1_w, fc1_b);
    k_heads<<<1, 896>>>(style_w, style_b, sem_w, sem_b, fun_w, fun_b,
                        aes_w, aes_b, (float*)d_out);
}